// round 1
// baseline (speedup 1.0000x reference)
#include <cuda_runtime.h>
#include <cstddef>

// CompetitiveNetwork: B=16384 rows, 64x64 K matrix shared across rows.
// Per row: 22 BF-steps + 21 AF-steps (64x64 matvecs), then Y = AF^T (K.W) BF + b.
//
// Layout: grid = 128 CTAs x 256 threads. Each CTA owns 128 rows for the whole
// fixed-point iteration (rows are independent -> no global sync). Two threads
// per row: thread half h in {0,1} owns output indices [32h, 32h+32) of each
// matvec. K (and K^T, and M^T = (K.W)^T) live in smem; K loads are uniform
// across a warp -> broadcast LDS.128. AF/BF state ping-pongs between smem
// buffers XA/XB with one __syncthreads per step. Inner math uses packed
// fma.rn.f32x2 (FFMA2) for 2x fp32 throughput.

typedef unsigned long long u64;

__device__ __forceinline__ void fma2(u64 &d, u64 a, u64 b) {
    asm("fma.rn.f32x2 %0, %1, %2, %0;" : "+l"(d) : "l"(a), "l"(b));
}
__device__ __forceinline__ u64 dup2(float x) {
    u64 r; unsigned xi = __float_as_uint(x);
    asm("mov.b64 %0, {%1, %1};" : "=l"(r) : "r"(xi));
    return r;
}
__device__ __forceinline__ void unpack2(u64 v, float &lo, float &hi) {
    unsigned a, b;
    asm("mov.b64 {%0, %1}, %2;" : "=r"(a), "=r"(b) : "l"(v));
    lo = __uint_as_float(a); hi = __uint_as_float(b);
}
__device__ __forceinline__ float rcpa(float x) {
    float r; asm("rcp.approx.f32 %0, %1;" : "=f"(r) : "f"(x)); return r;
}

#define N_DIM 64
#define ROWS_PER_CTA 128
#define THREADS 256

__global__ void __launch_bounds__(THREADS, 1)
competitive_net_kernel(const float* __restrict__ AT,
                       const float* __restrict__ Kraw,
                       const float* __restrict__ BTraw,
                       const float* __restrict__ Wraw,
                       const float* __restrict__ braw,
                       float* __restrict__ out)
{
    extern __shared__ float sm[];
    float* Ks  = sm;                  // [64][64] row-major: K[i][j]
    float* KTs = Ks  + 4096;          // [64][64]: KT[j][i] = K[i][j]
    float* MTs = KTs + 4096;          // [64][64]: MT[j][i] = K[i][j]*Wclip[i*64+j]
    float* BTs = MTs + 4096;          // [64]
    float* XA  = BTs + 64;            // [64][128]  AF state: XA[i*128+row]
    float* XB  = XA  + 8192;          // [64][128]  BF state
    float* PS  = XB  + 8192;          // [256] partial sums for Y

    const int tid  = threadIdx.x;
    const int row  = tid & 127;       // local row within CTA
    const int off  = (tid >> 7) * 32; // this thread's output half [off, off+32)
    const int bid  = blockIdx.x;

    // ---- setup: K, K^T, M^T = (K * clip(W))^T, BT -------------------------
    for (int idx = tid; idx < 4096; idx += THREADS) {
        int i = idx >> 6, j = idx & 63;
        float k = __expf(Kraw[idx]);
        k = fminf(k, 1000.0f);                 // exp >= 0, clip upper only
        Ks[idx] = k;
        KTs[j * 64 + i] = k;
        float w = fminf(fmaxf(Wraw[idx], -10.0f), 10.0f);
        MTs[j * 64 + i] = k * w;
    }
    if (tid < 64) BTs[tid] = fminf(__expf(BTraw[tid]), 1000.0f);

    // ---- stage AT tile coalesced into XA (initial AF = AT) ----------------
    {
        const float4* atg = reinterpret_cast<const float4*>(
            AT + (size_t)bid * (ROWS_PER_CTA * N_DIM));
        for (int idx = tid; idx < 2048; idx += THREADS) {
            float4 v = atg[idx];
            int flat = idx << 2;
            int r  = flat >> 6;
            int i0 = flat & 63;
            XA[(i0 + 0) * 128 + r] = v.x;
            XA[(i0 + 1) * 128 + r] = v.y;
            XA[(i0 + 2) * 128 + r] = v.z;
            XA[(i0 + 3) * 128 + r] = v.w;
        }
    }
    __syncthreads();

    // ---- cache this thread's AT half and BT half in registers -------------
    float at[32], bt[32];
    #pragma unroll
    for (int q = 0; q < 32; q++) {
        at[q] = XA[(off + q) * 128 + row];   // XA currently holds AT
        bt[q] = BTs[off + q];
    }

    // ---- 22 BF-steps interleaved with 21 AF-steps --------------------------
    #pragma unroll 1
    for (int it = 0; it < 22; ++it) {
        // BF-step: s_j = sum_i K[i][j] * AF_i ;  BF_j = BT_j / (s_j + 1)
        // reads XA, writes XB[j] for j in [off, off+32)
        u64 s2[16];
        #pragma unroll
        for (int q = 0; q < 16; q++) s2[q] = 0ULL;
        #pragma unroll 4
        for (int i = 0; i < 64; i++) {
            u64 a2 = dup2(XA[i * 128 + row]);
            const ulonglong2* kr =
                reinterpret_cast<const ulonglong2*>(Ks + i * 64 + off);
            #pragma unroll
            for (int q = 0; q < 8; q++) {
                ulonglong2 kk = kr[q];           // LDS.128, warp-uniform addr
                fma2(s2[2 * q + 0], kk.x, a2);
                fma2(s2[2 * q + 1], kk.y, a2);
            }
        }
        #pragma unroll
        for (int q = 0; q < 16; q++) {
            float lo, hi; unpack2(s2[q], lo, hi);
            XB[(off + 2 * q + 0) * 128 + row] = bt[2 * q + 0] * rcpa(lo + 1.0f);
            XB[(off + 2 * q + 1) * 128 + row] = bt[2 * q + 1] * rcpa(hi + 1.0f);
        }
        __syncthreads();

        if (it == 21) break;   // 22nd BF-step done; AF (in XA) stays from step 21

        // AF-step: t_i = sum_j K[i][j] * BF_j ;  AF_i = AT_i / (t_i + 1)
        // reads XB, writes XA[i] for i in [off, off+32)
        u64 t2[16];
        #pragma unroll
        for (int q = 0; q < 16; q++) t2[q] = 0ULL;
        #pragma unroll 4
        for (int j = 0; j < 64; j++) {
            u64 b2 = dup2(XB[j * 128 + row]);
            const ulonglong2* kr =
                reinterpret_cast<const ulonglong2*>(KTs + j * 64 + off);
            #pragma unroll
            for (int q = 0; q < 8; q++) {
                ulonglong2 kk = kr[q];
                fma2(t2[2 * q + 0], kk.x, b2);
                fma2(t2[2 * q + 1], kk.y, b2);
            }
        }
        #pragma unroll
        for (int q = 0; q < 16; q++) {
            float lo, hi; unpack2(t2[q], lo, hi);
            XA[(off + 2 * q + 0) * 128 + row] = at[2 * q + 0] * rcpa(lo + 1.0f);
            XA[(off + 2 * q + 1) * 128 + row] = at[2 * q + 1] * rcpa(hi + 1.0f);
        }
        __syncthreads();
    }

    // ---- final: y = sum_j BF_j * (sum_i M[i][j] * AF_i) + b ----------------
    // XA = final AF, XB = final BF. Load AF into registers once.
    float Xr[64];
    #pragma unroll
    for (int i = 0; i < 64; i++) Xr[i] = XA[i * 128 + row];

    float y = 0.0f;
    #pragma unroll 2
    for (int jj = 0; jj < 32; jj++) {
        int j = off + jj;
        float bf = XB[j * 128 + row];
        float v0 = 0.f, v1 = 0.f, v2 = 0.f, v3 = 0.f;
        const float4* mr = reinterpret_cast<const float4*>(MTs + j * 64);
        #pragma unroll
        for (int q = 0; q < 16; q++) {
            float4 m = mr[q];                    // LDS.128, warp-uniform addr
            v0 += m.x * Xr[4 * q + 0];
            v1 += m.y * Xr[4 * q + 1];
            v2 += m.z * Xr[4 * q + 2];
            v3 += m.w * Xr[4 * q + 3];
        }
        y += bf * ((v0 + v1) + (v2 + v3));
    }

    PS[tid] = y;
    __syncthreads();
    if (tid < ROWS_PER_CTA) {
        float bc = fminf(fmaxf(braw[0], -10.0f), 10.0f);
        out[(size_t)bid * ROWS_PER_CTA + tid] = PS[tid] + PS[tid + 128] + bc;
    }
}

extern "C" void kernel_launch(void* const* d_in, const int* in_sizes, int n_in,
                              void* d_out, int out_size)
{
    const float* AT    = (const float*)d_in[0];
    const float* Kraw  = (const float*)d_in[1];
    const float* BTraw = (const float*)d_in[2];
    const float* Wraw  = (const float*)d_in[3];
    const float* braw  = (const float*)d_in[4];
    float* out = (float*)d_out;

    const int B = in_sizes[0] / N_DIM;          // 16384
    const int grid = B / ROWS_PER_CTA;          // 128

    // Ks + KTs + MTs + BTs + XA + XB + PS
    const size_t smem_bytes =
        (size_t)(4096 * 3 + 64 + 8192 * 2 + 256) * sizeof(float); // 115968

    cudaFuncSetAttribute(competitive_net_kernel,
                         cudaFuncAttributeMaxDynamicSharedMemorySize,
                         (int)smem_bytes);

    competitive_net_kernel<<<grid, THREADS, smem_bytes>>>(
        AT, Kraw, BTraw, Wraw, braw, out);
}

// round 2
// speedup vs baseline: 1.2832x; 1.2832x over previous
#include <cuda_runtime.h>
#include <cstddef>

// CompetitiveNetwork: B=16384 rows, 64x64 K matrix shared across rows.
// Per row: 22 BF-steps + 21 AF-steps (64x64 matvecs), then Y = AF^T (K.W) BF + b.
//
// R1 change: thread decomposition (1 row x 32 cols) -> (2 rows x 16 cols).
// Each K broadcast LDS.128 now feeds 4 FFMA2 (2 rows) instead of 2, cutting
// L1 wavefronts/step from ~4.9K to ~3.3K per CTA (kernel was L1-bound at 73.5%).
// grid = 128 CTAs x 256 threads; CTA owns 128 rows for the whole iteration.

typedef unsigned long long u64;

__device__ __forceinline__ void fma2(u64 &d, u64 a, u64 b) {
    asm("fma.rn.f32x2 %0, %1, %2, %0;" : "+l"(d) : "l"(a), "l"(b));
}
__device__ __forceinline__ u64 dup2(float x) {
    u64 r; unsigned xi = __float_as_uint(x);
    asm("mov.b64 %0, {%1, %1};" : "=l"(r) : "r"(xi));
    return r;
}
__device__ __forceinline__ u64 pack2(float x, float y) {
    u64 r;
    asm("mov.b64 %0, {%1, %2};" : "=l"(r)
        : "r"(__float_as_uint(x)), "r"(__float_as_uint(y)));
    return r;
}
__device__ __forceinline__ void unpack2(u64 v, float &lo, float &hi) {
    unsigned a, b;
    asm("mov.b64 {%0, %1}, %2;" : "=r"(a), "=r"(b) : "l"(v));
    lo = __uint_as_float(a); hi = __uint_as_float(b);
}
__device__ __forceinline__ float rcpa(float x) {
    float r; asm("rcp.approx.f32 %0, %1;" : "=f"(r) : "f"(x)); return r;
}

#define N_DIM 64
#define ROWS_PER_CTA 128
#define THREADS 256

__global__ void __launch_bounds__(THREADS, 1)
competitive_net_kernel(const float* __restrict__ AT,
                       const float* __restrict__ Kraw,
                       const float* __restrict__ BTraw,
                       const float* __restrict__ Wraw,
                       const float* __restrict__ braw,
                       float* __restrict__ out)
{
    extern __shared__ float sm[];
    float* Ks  = sm;                  // [64][64] row-major: K[i][j]
    float* KTs = Ks  + 4096;          // [64][64]: KT[j][i] = K[i][j]
    float* Ms  = KTs + 4096;          // [64][64] row-major: K[i][j]*Wclip[i*64+j]
    float* BTs = Ms  + 4096;          // [64]
    float* XA  = BTs + 64;            // [64][128]  AF state: XA[i*128+row]
    float* XB  = XA  + 8192;          // [64][128]  BF state
    float* PS  = XB  + 8192;          // [4][128] partial sums for Y

    const int tid  = threadIdx.x;
    const int rg   = tid & 63;        // row group: rows 2rg, 2rg+1
    const int r0   = rg * 2;
    const int off  = (tid >> 6) * 16; // owned cols [off, off+16)
    const int bid  = blockIdx.x;

    // ---- setup: K, K^T, M = K*clip(W), BT ---------------------------------
    for (int idx = tid; idx < 4096; idx += THREADS) {
        int i = idx >> 6, j = idx & 63;
        float k = __expf(Kraw[idx]);
        k = fminf(k, 1000.0f);                 // exp >= 0, clip upper only
        Ks[idx] = k;
        KTs[j * 64 + i] = k;
        float w = fminf(fmaxf(Wraw[idx], -10.0f), 10.0f);
        Ms[idx] = k * w;
    }
    if (tid < 64) BTs[tid] = fminf(__expf(BTraw[tid]), 1000.0f);

    // ---- stage AT tile coalesced into XA (initial AF = AT) ----------------
    {
        const float4* atg = reinterpret_cast<const float4*>(
            AT + (size_t)bid * (ROWS_PER_CTA * N_DIM));
        for (int idx = tid; idx < 2048; idx += THREADS) {
            float4 v = atg[idx];
            int flat = idx << 2;
            int r  = flat >> 6;
            int i0 = flat & 63;
            XA[(i0 + 0) * 128 + r] = v.x;
            XA[(i0 + 1) * 128 + r] = v.y;
            XA[(i0 + 2) * 128 + r] = v.z;
            XA[(i0 + 3) * 128 + r] = v.w;
        }
    }
    __syncthreads();

    // ---- register caches: AT halves for both rows, BT slice ---------------
    float at0[16], at1[16], bt[16];
    #pragma unroll
    for (int q = 0; q < 16; q++) {
        at0[q] = XA[(off + q) * 128 + r0];
        at1[q] = XA[(off + q) * 128 + r0 + 1];
        bt[q]  = BTs[off + q];
    }

    u64 bf0p[8], bf1p[8];   // final BF (col pairs) per row, kept for Y epilogue

    // ---- 22 BF-steps interleaved with 21 AF-steps --------------------------
    #pragma unroll 1
    for (int it = 0; it < 22; ++it) {
        // BF-step: s_j = sum_i K[i][j] * AF_i ;  BF_j = BT_j / (s_j + 1)
        // s0[q] holds cols (2q,2q+1) for row r0; s1 for row r0+1.
        u64 s0[8], s1[8];
        #pragma unroll
        for (int q = 0; q < 8; q++) { s0[q] = 0ULL; s1[q] = 0ULL; }
        #pragma unroll 4
        for (int i = 0; i < 64; i++) {
            float2 a = *reinterpret_cast<const float2*>(XA + i * 128 + r0);
            u64 a0 = dup2(a.x), a1 = dup2(a.y);
            const ulonglong2* kr =
                reinterpret_cast<const ulonglong2*>(Ks + i * 64 + off);
            #pragma unroll
            for (int q = 0; q < 4; q++) {
                ulonglong2 kk = kr[q];           // LDS.128 broadcast
                fma2(s0[2 * q + 0], kk.x, a0);
                fma2(s0[2 * q + 1], kk.y, a0);
                fma2(s1[2 * q + 0], kk.x, a1);
                fma2(s1[2 * q + 1], kk.y, a1);
            }
        }
        #pragma unroll
        for (int q = 0; q < 8; q++) {
            float l0, h0, l1, h1;
            unpack2(s0[q], l0, h0);
            unpack2(s1[q], l1, h1);
            float b0l = bt[2 * q + 0] * rcpa(l0 + 1.0f);
            float b0h = bt[2 * q + 1] * rcpa(h0 + 1.0f);
            float b1l = bt[2 * q + 0] * rcpa(l1 + 1.0f);
            float b1h = bt[2 * q + 1] * rcpa(h1 + 1.0f);
            *reinterpret_cast<float2*>(XB + (off + 2 * q + 0) * 128 + r0) =
                make_float2(b0l, b1l);
            *reinterpret_cast<float2*>(XB + (off + 2 * q + 1) * 128 + r0) =
                make_float2(b0h, b1h);
            bf0p[q] = pack2(b0l, b0h);   // only the it==21 values are consumed
            bf1p[q] = pack2(b1l, b1h);
        }
        __syncthreads();

        if (it == 21) break;   // final BF done; AF (in XA) stays from step 21

        // AF-step: t_i = sum_j K[i][j] * BF_j ;  AF_i = AT_i / (t_i + 1)
        u64 t0[8], t1[8];
        #pragma unroll
        for (int q = 0; q < 8; q++) { t0[q] = 0ULL; t1[q] = 0ULL; }
        #pragma unroll 4
        for (int j = 0; j < 64; j++) {
            float2 b = *reinterpret_cast<const float2*>(XB + j * 128 + r0);
            u64 b0 = dup2(b.x), b1 = dup2(b.y);
            const ulonglong2* kr =
                reinterpret_cast<const ulonglong2*>(KTs + j * 64 + off);
            #pragma unroll
            for (int q = 0; q < 4; q++) {
                ulonglong2 kk = kr[q];
                fma2(t0[2 * q + 0], kk.x, b0);
                fma2(t0[2 * q + 1], kk.y, b0);
                fma2(t1[2 * q + 0], kk.x, b1);
                fma2(t1[2 * q + 1], kk.y, b1);
            }
        }
        #pragma unroll
        for (int q = 0; q < 8; q++) {
            float l0, h0, l1, h1;
            unpack2(t0[q], l0, h0);
            unpack2(t1[q], l1, h1);
            *reinterpret_cast<float2*>(XA + (off + 2 * q + 0) * 128 + r0) =
                make_float2(at0[2 * q + 0] * rcpa(l0 + 1.0f),
                            at1[2 * q + 0] * rcpa(l1 + 1.0f));
            *reinterpret_cast<float2*>(XA + (off + 2 * q + 1) * 128 + r0) =
                make_float2(at0[2 * q + 1] * rcpa(h0 + 1.0f),
                            at1[2 * q + 1] * rcpa(h1 + 1.0f));
        }
        __syncthreads();
    }

    // ---- final: y_row = sum_i AF_i * (sum_{j in mine} M[i][j] * BF_j) -----
    // XA = final AF; bf{0,1}p = final BF for owned cols (in registers).
    float y0 = 0.0f, y1 = 0.0f;
    #pragma unroll 2
    for (int i = 0; i < 64; i++) {
        float2 af = *reinterpret_cast<const float2*>(XA + i * 128 + r0);
        const ulonglong2* mr =
            reinterpret_cast<const ulonglong2*>(Ms + i * 64 + off);
        u64 g0 = 0ULL, g1 = 0ULL;
        #pragma unroll
        for (int q = 0; q < 4; q++) {
            ulonglong2 mm = mr[q];
            fma2(g0, mm.x, bf0p[2 * q + 0]);
            fma2(g0, mm.y, bf0p[2 * q + 1]);
            fma2(g1, mm.x, bf1p[2 * q + 0]);
            fma2(g1, mm.y, bf1p[2 * q + 1]);
        }
        float gl, gh;
        unpack2(g0, gl, gh); y0 = fmaf(af.x, gl + gh, y0);
        unpack2(g1, gl, gh); y1 = fmaf(af.y, gl + gh, y1);
    }

    PS[(tid >> 6) * 128 + r0]     = y0;
    PS[(tid >> 6) * 128 + r0 + 1] = y1;
    __syncthreads();
    if (tid < ROWS_PER_CTA) {
        float bc = fminf(fmaxf(braw[0], -10.0f), 10.0f);
        out[(size_t)bid * ROWS_PER_CTA + tid] =
            ((PS[tid] + PS[tid + 128]) + (PS[tid + 256] + PS[tid + 384])) + bc;
    }
}

extern "C" void kernel_launch(void* const* d_in, const int* in_sizes, int n_in,
                              void* d_out, int out_size)
{
    const float* AT    = (const float*)d_in[0];
    const float* Kraw  = (const float*)d_in[1];
    const float* BTraw = (const float*)d_in[2];
    const float* Wraw  = (const float*)d_in[3];
    const float* braw  = (const float*)d_in[4];
    float* out = (float*)d_out;

    const int B = in_sizes[0] / N_DIM;          // 16384
    const int grid = B / ROWS_PER_CTA;          // 128

    // Ks + KTs + Ms + BTs + XA + XB + PS
    const size_t smem_bytes =
        (size_t)(4096 * 3 + 64 + 8192 * 2 + 512) * sizeof(float); // 116992

    cudaFuncSetAttribute(competitive_net_kernel,
                         cudaFuncAttributeMaxDynamicSharedMemorySize,
                         (int)smem_bytes);

    competitive_net_kernel<<<grid, THREADS, smem_bytes>>>(
        AT, Kraw, BTraw, Wraw, braw, out);
}

// round 4
// speedup vs baseline: 1.9322x; 1.5058x over previous
#include <cuda_runtime.h>
#include <cuda_bf16.h>
#include <cstdint>
#include <cstddef>

// CompetitiveNetwork via classic mma.sync (m16n8k16 bf16, fp32 accum) —
// base-PTX only (tcgen05 is sm_103a-gated and this toolchain targets sm_103).
//
// Per CTA: 128 rows, 4 warps, warp w owns rows [32w, 32w+32) for ALL 43 steps.
// Key property: D-fragment (c0,c1)=(row g, col 2t,2t+1) is exactly the
// A-fragment position (row g, k 2t,2t+1) of the next step -> the state stays
// in registers across the whole iteration. No shuffles, no smem state, no
// __syncthreads after setup. Only static B matrices (KT/K/MT, bf16 hi+lo
// split) are read from smem per step. 3 MMAs per product term recover ~2^-16
// relative precision.

#define THREADS 128
#define ROWS_PER_CTA 128
#define N_DIM 64

typedef unsigned int u32;

// B matrix smem layout: [n][k] bf16, row stride 72 (=144B) -> conflict-free
// frag loads. 6 matrices: 0/1 = KT hi/lo (BF-step), 2/3 = K hi/lo (AF-step),
// 4/5 = MT hi/lo (epilogue). Each 64*72*2 = 9216 bytes.
#define MAT_BYTES 9216
#define AT_OFF    (6 * MAT_BYTES)          // 55296
#define AT_STRIDE 66                        // f32 words per row (128 rows)
#define SMEM_TOTAL (AT_OFF + 128 * AT_STRIDE * 4)   // 89088

__device__ __forceinline__ float rcpa(float x) {
    float r; asm("rcp.approx.f32 %0, %1;" : "=f"(r) : "f"(x)); return r;
}
// pack bf16x2: low half = lo_elem, high half = hi_elem
__device__ __forceinline__ u32 packbf(float lo_elem, float hi_elem) {
    u32 r; asm("cvt.rn.bf16x2.f32 %0, %1, %2;" : "=r"(r)
               : "f"(hi_elem), "f"(lo_elem));
    return r;
}
// split (x0,x1) into bf16 hi pair + residual lo pair
__device__ __forceinline__ void split2(float x0, float x1, u32 &hi, u32 &lo) {
    hi = packbf(x0, x1);
    float h0 = __uint_as_float(hi << 16);
    float h1 = __uint_as_float(hi & 0xFFFF0000u);
    lo = packbf(x0 - h0, x1 - h1);
}

#define MMA(d, a, b0, b1)                                                      \
    asm("mma.sync.aligned.m16n8k16.row.col.f32.bf16.bf16.f32 "                 \
        "{%0,%1,%2,%3}, {%4,%5,%6,%7}, {%8,%9}, {%0,%1,%2,%3};"                \
        : "+f"((d)[0]), "+f"((d)[1]), "+f"((d)[2]), "+f"((d)[3])               \
        : "r"((a)[0]), "r"((a)[1]), "r"((a)[2]), "r"((a)[3]),                  \
          "r"(b0), "r"(b1))

__global__ void __launch_bounds__(THREADS, 1)
cnet_mma_kernel(const float* __restrict__ AT,
                const float* __restrict__ Kraw,
                const float* __restrict__ BTraw,
                const float* __restrict__ Wraw,
                const float* __restrict__ braw,
                float* __restrict__ out)
{
    extern __shared__ char smc[];
    __nv_bfloat16* mats = reinterpret_cast<__nv_bfloat16*>(smc);
    float* ats = reinterpret_cast<float*>(smc + AT_OFF);   // [128][66] f32

    const int tid  = threadIdx.x;
    const int w    = tid >> 5;          // warp 0..3 -> rows [32w, 32w+32)
    const int lane = tid & 31;
    const int g    = lane >> 2;         // group row 0..7
    const int t    = lane & 3;          // thread-in-group 0..3
    const int rb   = w * 32;            // warp row base (CTA-local)
    const int bid  = blockIdx.x;

    // ---- setup: exp/clip K, build split B matrices + AT tile ---------------
    for (int idx = tid; idx < 4096; idx += THREADS) {
        int i = idx >> 6, j = idx & 63;
        float k = fminf(__expf(Kraw[idx]), 1000.0f);
        float wv = fminf(fmaxf(Wraw[idx], -10.0f), 10.0f);
        float m = k * wv;
        __nv_bfloat16 kh = __float2bfloat16_rn(k);
        __nv_bfloat16 kl = __float2bfloat16_rn(k - __bfloat162float(kh));
        __nv_bfloat16 mh = __float2bfloat16_rn(m);
        __nv_bfloat16 ml = __float2bfloat16_rn(m - __bfloat162float(mh));
        mats[0 * 4608 + j * 72 + i] = kh;   // KT hi  (BF-step B)
        mats[1 * 4608 + j * 72 + i] = kl;   // KT lo
        mats[2 * 4608 + i * 72 + j] = kh;   // K  hi  (AF-step B)
        mats[3 * 4608 + i * 72 + j] = kl;   // K  lo
        mats[4 * 4608 + j * 72 + i] = mh;   // MT hi  (epilogue B)
        mats[5 * 4608 + j * 72 + i] = ml;   // MT lo
    }
    {
        const float4* atg = reinterpret_cast<const float4*>(
            AT + (size_t)bid * (ROWS_PER_CTA * N_DIM));
        for (int idx = tid; idx < 2048; idx += THREADS) {
            float4 v = atg[idx];
            int r = idx >> 4, c = (idx & 15) << 2;
            float* p = ats + r * AT_STRIDE + c;
            p[0] = v.x; p[1] = v.y; p[2] = v.z; p[3] = v.w;
        }
    }
    // BT cache: col = 8*nt + 2t + h  ->  btv[2*nt + h]
    float btv[16];
    #pragma unroll
    for (int nt = 0; nt < 8; nt++) {
        btv[2 * nt + 0] = fminf(__expf(BTraw[8 * nt + 2 * t + 0]), 1000.0f);
        btv[2 * nt + 1] = fminf(__expf(BTraw[8 * nt + 2 * t + 1]), 1000.0f);
    }
    __syncthreads();

    // ---- fragment registers -------------------------------------------------
    float d[2][8][4];          // D frags: [mt][nt][c]
    u32 ah[2][4][4], al[2][4][4];   // A frags hi/lo: [mt][kt][reg]

    // initial A = split(AT) from smem
    #pragma unroll
    for (int mt = 0; mt < 2; mt++) {
        int rlo = (rb + 16 * mt + g) * AT_STRIDE;
        int rhi = (rb + 16 * mt + 8 + g) * AT_STRIDE;
        #pragma unroll
        for (int kt = 0; kt < 4; kt++) {
            int cb = 16 * kt + 2 * t;
            float2 p0 = *reinterpret_cast<const float2*>(ats + rlo + cb);
            float2 p1 = *reinterpret_cast<const float2*>(ats + rhi + cb);
            float2 p2 = *reinterpret_cast<const float2*>(ats + rlo + cb + 8);
            float2 p3 = *reinterpret_cast<const float2*>(ats + rhi + cb + 8);
            split2(p0.x, p0.y, ah[mt][kt][0], al[mt][kt][0]);
            split2(p1.x, p1.y, ah[mt][kt][1], al[mt][kt][1]);
            split2(p2.x, p2.y, ah[mt][kt][2], al[mt][kt][2]);
            split2(p3.x, p3.y, ah[mt][kt][3], al[mt][kt][3]);
        }
    }

    const u32* __restrict__ matw = reinterpret_cast<const u32*>(smc);
    const int gt = 36 * g + t;          // u32 word offset of (n=g, k=2t)

    // 3-way split MMA phase over one B-matrix pair (hi at MH, lo at MH+1)
#define MMA_PHASE(MH)                                                          \
    do {                                                                       \
        _Pragma("unroll")                                                      \
        for (int mt = 0; mt < 2; mt++)                                         \
            _Pragma("unroll")                                                  \
            for (int nt = 0; nt < 8; nt++)                                     \
                _Pragma("unroll")                                              \
                for (int c = 0; c < 4; c++) d[mt][nt][c] = 0.0f;               \
        _Pragma("unroll")                                                      \
        for (int nt = 0; nt < 8; nt++) {                                       \
            const u32* BH = matw + (MH) * 2304 + 288 * nt + gt;                \
            const u32* BL = BH + 2304;                                         \
            _Pragma("unroll")                                                  \
            for (int kt = 0; kt < 4; kt++) {                                   \
                u32 bh0 = BH[8 * kt], bh1 = BH[8 * kt + 4];                    \
                u32 bl0 = BL[8 * kt], bl1 = BL[8 * kt + 4];                    \
                _Pragma("unroll")                                              \
                for (int mt = 0; mt < 2; mt++) {                               \
                    MMA(d[mt][nt], ah[mt][kt], bh0, bh1);                      \
                    MMA(d[mt][nt], al[mt][kt], bh0, bh1);                      \
                    MMA(d[mt][nt], ah[mt][kt], bl0, bl1);                      \
                }                                                              \
            }                                                                  \
        }                                                                      \
    } while (0)

    // repack d (post-nonlinearity fp32) into A frags (in-lane, no shuffle)
#define REPACK()                                                               \
    do {                                                                       \
        _Pragma("unroll")                                                      \
        for (int mt = 0; mt < 2; mt++)                                         \
            _Pragma("unroll")                                                  \
            for (int kt = 0; kt < 4; kt++) {                                   \
                split2(d[mt][2*kt][0],   d[mt][2*kt][1],                       \
                       ah[mt][kt][0], al[mt][kt][0]);                          \
                split2(d[mt][2*kt][2],   d[mt][2*kt][3],                       \
                       ah[mt][kt][1], al[mt][kt][1]);                          \
                split2(d[mt][2*kt+1][0], d[mt][2*kt+1][1],                     \
                       ah[mt][kt][2], al[mt][kt][2]);                          \
                split2(d[mt][2*kt+1][2], d[mt][2*kt+1][3],                     \
                       ah[mt][kt][3], al[mt][kt][3]);                          \
            }                                                                  \
    } while (0)

    // ---- 22 BF-steps interleaved with 21 AF-steps ---------------------------
    #pragma unroll 1
    for (int it = 0; it < 22; ++it) {
        // BF-step: S = AF @ K (B = KT mats 0/1); BF = BT * rcp(S + 1)
        MMA_PHASE(0);
        #pragma unroll
        for (int mt = 0; mt < 2; mt++)
            #pragma unroll
            for (int nt = 0; nt < 8; nt++) {
                d[mt][nt][0] = btv[2*nt+0] * rcpa(d[mt][nt][0] + 1.0f);
                d[mt][nt][1] = btv[2*nt+1] * rcpa(d[mt][nt][1] + 1.0f);
                d[mt][nt][2] = btv[2*nt+0] * rcpa(d[mt][nt][2] + 1.0f);
                d[mt][nt][3] = btv[2*nt+1] * rcpa(d[mt][nt][3] + 1.0f);
            }

        if (it == 21) break;   // d = final BF (fp32); ah/al = final AF

        REPACK();              // A <- BF

        // AF-step: T = BF @ K^T (B = K mats 2/3); AF = AT * rcp(T + 1)
        MMA_PHASE(2);
        #pragma unroll
        for (int mt = 0; mt < 2; mt++) {
            int rlo = (rb + 16 * mt + g) * AT_STRIDE;
            int rhi = (rb + 16 * mt + 8 + g) * AT_STRIDE;
            #pragma unroll
            for (int nt = 0; nt < 8; nt++) {
                int cb = 8 * nt + 2 * t;
                float2 plo = *reinterpret_cast<const float2*>(ats + rlo + cb);
                float2 phi = *reinterpret_cast<const float2*>(ats + rhi + cb);
                d[mt][nt][0] = plo.x * rcpa(d[mt][nt][0] + 1.0f);
                d[mt][nt][1] = plo.y * rcpa(d[mt][nt][1] + 1.0f);
                d[mt][nt][2] = phi.x * rcpa(d[mt][nt][2] + 1.0f);
                d[mt][nt][3] = phi.y * rcpa(d[mt][nt][3] + 1.0f);
            }
        }

        REPACK();              // A <- AF
    }

    // ---- stash final BF (fp32) into the AT region (AT is dead now) ---------
    // Same warp/lane writes and reads its own positions: no sync needed.
    #pragma unroll
    for (int mt = 0; mt < 2; mt++) {
        int rlo = (rb + 16 * mt + g) * AT_STRIDE;
        int rhi = (rb + 16 * mt + 8 + g) * AT_STRIDE;
        #pragma unroll
        for (int nt = 0; nt < 8; nt++) {
            int cb = 8 * nt + 2 * t;
            *reinterpret_cast<float2*>(ats + rlo + cb) =
                make_float2(d[mt][nt][0], d[mt][nt][1]);
            *reinterpret_cast<float2*>(ats + rhi + cb) =
                make_float2(d[mt][nt][2], d[mt][nt][3]);
        }
    }

    // ---- epilogue: H = AF @ M (B = MT mats 4/5); y_r = sum_j BF[r,j] H[r,j]
    MMA_PHASE(4);

    float y[2][2] = {{0.f, 0.f}, {0.f, 0.f}};
    #pragma unroll
    for (int mt = 0; mt < 2; mt++) {
        int rlo = (rb + 16 * mt + g) * AT_STRIDE;
        int rhi = (rb + 16 * mt + 8 + g) * AT_STRIDE;
        #pragma unroll
        for (int nt = 0; nt < 8; nt++) {
            int cb = 8 * nt + 2 * t;
            float2 blo = *reinterpret_cast<const float2*>(ats + rlo + cb);
            float2 bhi = *reinterpret_cast<const float2*>(ats + rhi + cb);
            y[mt][0] = fmaf(blo.x, d[mt][nt][0],
                       fmaf(blo.y, d[mt][nt][1], y[mt][0]));
            y[mt][1] = fmaf(bhi.x, d[mt][nt][2],
                       fmaf(bhi.y, d[mt][nt][3], y[mt][1]));
        }
    }

    // reduce over the 4 lanes of each g-group (t = 0..3)
    #pragma unroll
    for (int mt = 0; mt < 2; mt++)
        #pragma unroll
        for (int rh = 0; rh < 2; rh++) {
            float v = y[mt][rh];
            v += __shfl_xor_sync(0xFFFFFFFFu, v, 1);
            v += __shfl_xor_sync(0xFFFFFFFFu, v, 2);
            y[mt][rh] = v;
        }

    if (t == 0) {
        float bc = fminf(fmaxf(braw[0], -10.0f), 10.0f);
        size_t base = (size_t)bid * ROWS_PER_CTA + rb + g;
        out[base +  0] = y[0][0] + bc;   // row 16*0 + 0 + g
        out[base +  8] = y[0][1] + bc;   // row 16*0 + 8 + g
        out[base + 16] = y[1][0] + bc;   // row 16*1 + 0 + g
        out[base + 24] = y[1][1] + bc;   // row 16*1 + 8 + g
    }
}

extern "C" void kernel_launch(void* const* d_in, const int* in_sizes, int n_in,
                              void* d_out, int out_size)
{
    const float* AT    = (const float*)d_in[0];
    const float* Kraw  = (const float*)d_in[1];
    const float* BTraw = (const float*)d_in[2];
    const float* Wraw  = (const float*)d_in[3];
    const float* braw  = (const float*)d_in[4];
    float* out = (float*)d_out;

    const int B = in_sizes[0] / N_DIM;          // 16384
    const int grid = B / ROWS_PER_CTA;          // 128

    cudaFuncSetAttribute(cnet_mma_kernel,
                         cudaFuncAttributeMaxDynamicSharedMemorySize,
                         SMEM_TOTAL);

    cnet_mma_kernel<<<grid, THREADS, SMEM_TOTAL>>>(
        AT, Kraw, BTraw, Wraw, braw, out);
}

// round 5
// speedup vs baseline: 2.9190x; 1.5107x over previous
#include <cuda_runtime.h>
#include <cuda_bf16.h>
#include <cstdint>
#include <cstddef>

// CompetitiveNetwork via classic mma.sync (m16n8k16 bf16, fp32 accum).
// R4: 16 rows per warp (one m16 tile), 8 warps/CTA (256 thr), grid=128.
// Fixes R3's regs=255 spills and 1-warp/SMSP latency exposure (occ 6.2%,
// tensor 23.7%). State (D-frag -> A-frag, same lane positions) stays in
// registers across all 43 steps; no shuffles, no syncs in the loop.
// bf16 hi+lo split, 3 MMAs per logical product -> ~2^-16 relative precision.

#define THREADS 256
#define ROWS_PER_CTA 128
#define N_DIM 64

typedef unsigned int u32;

// B matrices: [n][k] bf16, row stride 72 (144B) -> conflict-free frag loads.
// 0/1 = KT hi/lo (BF-step), 2/3 = K hi/lo (AF-step), 4/5 = MT hi/lo (epilogue)
#define MAT_BYTES 9216
#define AT_OFF    (6 * MAT_BYTES)          // 55296
#define AT_STRIDE 66                        // f32 words per row
#define SMEM_TOTAL (AT_OFF + 128 * AT_STRIDE * 4)   // 89088

__device__ __forceinline__ float rcpa(float x) {
    float r; asm("rcp.approx.f32 %0, %1;" : "=f"(r) : "f"(x)); return r;
}
__device__ __forceinline__ u32 packbf(float lo_elem, float hi_elem) {
    u32 r; asm("cvt.rn.bf16x2.f32 %0, %1, %2;" : "=r"(r)
               : "f"(hi_elem), "f"(lo_elem));
    return r;
}
__device__ __forceinline__ void split2(float x0, float x1, u32 &hi, u32 &lo) {
    hi = packbf(x0, x1);
    float h0 = __uint_as_float(hi << 16);
    float h1 = __uint_as_float(hi & 0xFFFF0000u);
    lo = packbf(x0 - h0, x1 - h1);
}

#define MMA(d, a, b0, b1)                                                      \
    asm("mma.sync.aligned.m16n8k16.row.col.f32.bf16.bf16.f32 "                 \
        "{%0,%1,%2,%3}, {%4,%5,%6,%7}, {%8,%9}, {%0,%1,%2,%3};"                \
        : "+f"((d)[0]), "+f"((d)[1]), "+f"((d)[2]), "+f"((d)[3])               \
        : "r"((a)[0]), "r"((a)[1]), "r"((a)[2]), "r"((a)[3]),                  \
          "r"(b0), "r"(b1))

__global__ void __launch_bounds__(THREADS, 1)
cnet_mma_kernel(const float* __restrict__ AT,
                const float* __restrict__ Kraw,
                const float* __restrict__ BTraw,
                const float* __restrict__ Wraw,
                const float* __restrict__ braw,
                float* __restrict__ out)
{
    extern __shared__ char smc[];
    __nv_bfloat16* mats = reinterpret_cast<__nv_bfloat16*>(smc);
    float* ats = reinterpret_cast<float*>(smc + AT_OFF);   // [128][66] f32

    const int tid  = threadIdx.x;
    const int w    = tid >> 5;          // warp 0..7 -> rows [16w, 16w+16)
    const int lane = tid & 31;
    const int g    = lane >> 2;         // group row 0..7
    const int t    = lane & 3;          // thread-in-group 0..3
    const int rb   = w * 16;            // warp row base (CTA-local)
    const int bid  = blockIdx.x;

    // ---- setup: exp/clip K, build split B matrices + AT tile ---------------
    for (int idx = tid; idx < 4096; idx += THREADS) {
        int i = idx >> 6, j = idx & 63;
        float k = fminf(__expf(Kraw[idx]), 1000.0f);
        float wv = fminf(fmaxf(Wraw[idx], -10.0f), 10.0f);
        float m = k * wv;
        __nv_bfloat16 kh = __float2bfloat16_rn(k);
        __nv_bfloat16 kl = __float2bfloat16_rn(k - __bfloat162float(kh));
        __nv_bfloat16 mh = __float2bfloat16_rn(m);
        __nv_bfloat16 ml = __float2bfloat16_rn(m - __bfloat162float(mh));
        mats[0 * 4608 + j * 72 + i] = kh;   // KT hi  (BF-step B)
        mats[1 * 4608 + j * 72 + i] = kl;   // KT lo
        mats[2 * 4608 + i * 72 + j] = kh;   // K  hi  (AF-step B)
        mats[3 * 4608 + i * 72 + j] = kl;   // K  lo
        mats[4 * 4608 + j * 72 + i] = mh;   // MT hi  (epilogue B)
        mats[5 * 4608 + j * 72 + i] = ml;   // MT lo
    }
    {
        const float4* atg = reinterpret_cast<const float4*>(
            AT + (size_t)bid * (ROWS_PER_CTA * N_DIM));
        for (int idx = tid; idx < 2048; idx += THREADS) {
            float4 v = atg[idx];
            int r = idx >> 4, c = (idx & 15) << 2;
            float* p = ats + r * AT_STRIDE + c;
            p[0] = v.x; p[1] = v.y; p[2] = v.z; p[3] = v.w;
        }
    }
    // BT cache: col = 8*nt + 2t + h  ->  btv[2*nt + h]
    float btv[16];
    #pragma unroll
    for (int nt = 0; nt < 8; nt++) {
        btv[2 * nt + 0] = fminf(__expf(BTraw[8 * nt + 2 * t + 0]), 1000.0f);
        btv[2 * nt + 1] = fminf(__expf(BTraw[8 * nt + 2 * t + 1]), 1000.0f);
    }
    __syncthreads();

    // ---- fragment registers -------------------------------------------------
    float d[8][4];            // D frags: [nt][c]
    u32 ah[4][4], al[4][4];   // A frags hi/lo: [kt][reg]

    const int rlo = (rb + g) * AT_STRIDE;
    const int rhi = (rb + 8 + g) * AT_STRIDE;

    // initial A = split(AT) from smem
    #pragma unroll
    for (int kt = 0; kt < 4; kt++) {
        int cb = 16 * kt + 2 * t;
        float2 p0 = *reinterpret_cast<const float2*>(ats + rlo + cb);
        float2 p1 = *reinterpret_cast<const float2*>(ats + rhi + cb);
        float2 p2 = *reinterpret_cast<const float2*>(ats + rlo + cb + 8);
        float2 p3 = *reinterpret_cast<const float2*>(ats + rhi + cb + 8);
        split2(p0.x, p0.y, ah[kt][0], al[kt][0]);
        split2(p1.x, p1.y, ah[kt][1], al[kt][1]);
        split2(p2.x, p2.y, ah[kt][2], al[kt][2]);
        split2(p3.x, p3.y, ah[kt][3], al[kt][3]);
    }

    const u32* __restrict__ matw = reinterpret_cast<const u32*>(smc);
    const int gt = 36 * g + t;          // u32 word offset of (n=g, k=2t)

    // 3-way split MMA phase over one B-matrix pair (hi at MH, lo at MH+1)
#define MMA_PHASE(MH)                                                          \
    do {                                                                       \
        _Pragma("unroll")                                                      \
        for (int nt = 0; nt < 8; nt++)                                         \
            _Pragma("unroll")                                                  \
            for (int c = 0; c < 4; c++) d[nt][c] = 0.0f;                       \
        _Pragma("unroll")                                                      \
        for (int nt = 0; nt < 8; nt++) {                                       \
            const u32* BH = matw + (MH) * 2304 + 288 * nt + gt;                \
            const u32* BL = BH + 2304;                                         \
            _Pragma("unroll")                                                  \
            for (int kt = 0; kt < 4; kt++) {                                   \
                u32 bh0 = BH[8 * kt], bh1 = BH[8 * kt + 4];                    \
                u32 bl0 = BL[8 * kt], bl1 = BL[8 * kt + 4];                    \
                MMA(d[nt], ah[kt], bh0, bh1);                                  \
                MMA(d[nt], al[kt], bh0, bh1);                                  \
                MMA(d[nt], ah[kt], bl0, bl1);                                  \
            }                                                                  \
        }                                                                      \
    } while (0)

    // repack d (post-nonlinearity fp32) into A frags (in-lane, no shuffle)
#define REPACK()                                                               \
    do {                                                                       \
        _Pragma("unroll")                                                      \
        for (int kt = 0; kt < 4; kt++) {                                       \
            split2(d[2*kt][0],   d[2*kt][1],   ah[kt][0], al[kt][0]);          \
            split2(d[2*kt][2],   d[2*kt][3],   ah[kt][1], al[kt][1]);          \
            split2(d[2*kt+1][0], d[2*kt+1][1], ah[kt][2], al[kt][2]);          \
            split2(d[2*kt+1][2], d[2*kt+1][3], ah[kt][3], al[kt][3]);          \
        }                                                                      \
    } while (0)

    // ---- 22 BF-steps interleaved with 21 AF-steps ---------------------------
    #pragma unroll 1
    for (int it = 0; it < 22; ++it) {
        // BF-step: S = AF @ K (B = KT mats 0/1); BF = BT * rcp(S + 1)
        MMA_PHASE(0);
        #pragma unroll
        for (int nt = 0; nt < 8; nt++) {
            d[nt][0] = btv[2*nt+0] * rcpa(d[nt][0] + 1.0f);
            d[nt][1] = btv[2*nt+1] * rcpa(d[nt][1] + 1.0f);
            d[nt][2] = btv[2*nt+0] * rcpa(d[nt][2] + 1.0f);
            d[nt][3] = btv[2*nt+1] * rcpa(d[nt][3] + 1.0f);
        }

        if (it == 21) break;   // d = final BF (fp32); ah/al = final AF

        REPACK();              // A <- BF

        // AF-step: T = BF @ K^T (B = K mats 2/3); AF = AT * rcp(T + 1)
        MMA_PHASE(2);
        #pragma unroll
        for (int nt = 0; nt < 8; nt++) {
            int cb = 8 * nt + 2 * t;
            float2 plo = *reinterpret_cast<const float2*>(ats + rlo + cb);
            float2 phi = *reinterpret_cast<const float2*>(ats + rhi + cb);
            d[nt][0] = plo.x * rcpa(d[nt][0] + 1.0f);
            d[nt][1] = plo.y * rcpa(d[nt][1] + 1.0f);
            d[nt][2] = phi.x * rcpa(d[nt][2] + 1.0f);
            d[nt][3] = phi.y * rcpa(d[nt][3] + 1.0f);
        }

        REPACK();              // A <- AF
    }

    // ---- stash final BF (fp32) into the AT region (AT is dead now) ---------
    // Same warp/lane writes and reads its own positions: no sync needed.
    #pragma unroll
    for (int nt = 0; nt < 8; nt++) {
        int cb = 8 * nt + 2 * t;
        *reinterpret_cast<float2*>(ats + rlo + cb) =
            make_float2(d[nt][0], d[nt][1]);
        *reinterpret_cast<float2*>(ats + rhi + cb) =
            make_float2(d[nt][2], d[nt][3]);
    }

    // ---- epilogue: H = AF @ M (B = MT mats 4/5); y_r = sum_j BF[r,j] H[r,j]
    MMA_PHASE(4);

    float y0 = 0.f, y1 = 0.f;
    #pragma unroll
    for (int nt = 0; nt < 8; nt++) {
        int cb = 8 * nt + 2 * t;
        float2 blo = *reinterpret_cast<const float2*>(ats + rlo + cb);
        float2 bhi = *reinterpret_cast<const float2*>(ats + rhi + cb);
        y0 = fmaf(blo.x, d[nt][0], fmaf(blo.y, d[nt][1], y0));
        y1 = fmaf(bhi.x, d[nt][2], fmaf(bhi.y, d[nt][3], y1));
    }

    // reduce over the 4 lanes of each g-group (t = 0..3)
    y0 += __shfl_xor_sync(0xFFFFFFFFu, y0, 1);
    y0 += __shfl_xor_sync(0xFFFFFFFFu, y0, 2);
    y1 += __shfl_xor_sync(0xFFFFFFFFu, y1, 1);
    y1 += __shfl_xor_sync(0xFFFFFFFFu, y1, 2);

    if (t == 0) {
        float bc = fminf(fmaxf(braw[0], -10.0f), 10.0f);
        size_t base = (size_t)bid * ROWS_PER_CTA + rb + g;
        out[base + 0] = y0 + bc;   // row rb + g
        out[base + 8] = y1 + bc;   // row rb + 8 + g
    }
}

extern "C" void kernel_launch(void* const* d_in, const int* in_sizes, int n_in,
                              void* d_out, int out_size)
{
    const float* AT    = (const float*)d_in[0];
    const float* Kraw  = (const float*)d_in[1];
    const float* BTraw = (const float*)d_in[2];
    const float* Wraw  = (const float*)d_in[3];
    const float* braw  = (const float*)d_in[4];
    float* out = (float*)d_out;

    const int B = in_sizes[0] / N_DIM;          // 16384
    const int grid = B / ROWS_PER_CTA;          // 128

    cudaFuncSetAttribute(cnet_mma_kernel,
                         cudaFuncAttributeMaxDynamicSharedMemorySize,
                         SMEM_TOTAL);

    cnet_mma_kernel<<<grid, THREADS, SMEM_TOTAL>>>(
        AT, Kraw, BTraw, Wraw, braw, out);
}

// round 6
// speedup vs baseline: 4.3421x; 1.4875x over previous
#include <cuda_runtime.h>
#include <cuda_bf16.h>
#include <cstdint>
#include <cstddef>

// CompetitiveNetwork via mma.sync (m16n8k16 bf16, fp32 accum).
// R5: convergence-aware precision schedule. Fixed-point iteration -> early
// step errors are transient. Iterations 0..15 use single-MMA bf16 (Ah*Bh);
// iterations 16..21 + epilogue use the 3-term split (Ah*Bh+Al*Bh+Ah*Bl) for
// ~2^-16 relative precision at the converged answer. Tensor work -49%.
// Also: kt-outer MMA order so same-accumulator HMMAs are >=3 apart.
// 8 warps/CTA, 16 rows/warp, state lives in registers all 43 steps.

#define THREADS 256
#define ROWS_PER_CTA 128
#define N_DIM 64
#define PREC_START 16

typedef unsigned int u32;

// B matrices: [n][k] bf16, row stride 72 (144B) -> conflict-free frag loads.
// 0/1 = KT hi/lo (BF-step), 2/3 = K hi/lo (AF-step), 4/5 = MT hi/lo (epilogue)
#define MAT_BYTES 9216
#define AT_OFF    (6 * MAT_BYTES)          // 55296
#define AT_STRIDE 66                        // f32 words per row
#define SMEM_TOTAL (AT_OFF + 128 * AT_STRIDE * 4)   // 89088

__device__ __forceinline__ float rcpa(float x) {
    float r; asm("rcp.approx.f32 %0, %1;" : "=f"(r) : "f"(x)); return r;
}
__device__ __forceinline__ u32 packbf(float lo_elem, float hi_elem) {
    u32 r; asm("cvt.rn.bf16x2.f32 %0, %1, %2;" : "=r"(r)
               : "f"(hi_elem), "f"(lo_elem));
    return r;
}
__device__ __forceinline__ void split2(float x0, float x1, u32 &hi, u32 &lo) {
    hi = packbf(x0, x1);
    float h0 = __uint_as_float(hi << 16);
    float h1 = __uint_as_float(hi & 0xFFFF0000u);
    lo = packbf(x0 - h0, x1 - h1);
}

#define MMA(d, a, b0, b1)                                                      \
    asm("mma.sync.aligned.m16n8k16.row.col.f32.bf16.bf16.f32 "                 \
        "{%0,%1,%2,%3}, {%4,%5,%6,%7}, {%8,%9}, {%0,%1,%2,%3};"                \
        : "+f"((d)[0]), "+f"((d)[1]), "+f"((d)[2]), "+f"((d)[3])               \
        : "r"((a)[0]), "r"((a)[1]), "r"((a)[2]), "r"((a)[3]),                  \
          "r"(b0), "r"(b1))

__global__ void __launch_bounds__(THREADS, 1)
cnet_mma_kernel(const float* __restrict__ AT,
                const float* __restrict__ Kraw,
                const float* __restrict__ BTraw,
                const float* __restrict__ Wraw,
                const float* __restrict__ braw,
                float* __restrict__ out)
{
    extern __shared__ char smc[];
    __nv_bfloat16* mats = reinterpret_cast<__nv_bfloat16*>(smc);
    float* ats = reinterpret_cast<float*>(smc + AT_OFF);   // [128][66] f32

    const int tid  = threadIdx.x;
    const int w    = tid >> 5;          // warp 0..7 -> rows [16w, 16w+16)
    const int lane = tid & 31;
    const int g    = lane >> 2;         // group row 0..7
    const int t    = lane & 3;          // thread-in-group 0..3
    const int rb   = w * 16;            // warp row base (CTA-local)
    const int bid  = blockIdx.x;

    // ---- setup: exp/clip K, build split B matrices + AT tile ---------------
    for (int idx = tid; idx < 4096; idx += THREADS) {
        int i = idx >> 6, j = idx & 63;
        float k = fminf(__expf(Kraw[idx]), 1000.0f);
        float wv = fminf(fmaxf(Wraw[idx], -10.0f), 10.0f);
        float m = k * wv;
        __nv_bfloat16 kh = __float2bfloat16_rn(k);
        __nv_bfloat16 kl = __float2bfloat16_rn(k - __bfloat162float(kh));
        __nv_bfloat16 mh = __float2bfloat16_rn(m);
        __nv_bfloat16 ml = __float2bfloat16_rn(m - __bfloat162float(mh));
        mats[0 * 4608 + j * 72 + i] = kh;   // KT hi  (BF-step B)
        mats[1 * 4608 + j * 72 + i] = kl;   // KT lo
        mats[2 * 4608 + i * 72 + j] = kh;   // K  hi  (AF-step B)
        mats[3 * 4608 + i * 72 + j] = kl;   // K  lo
        mats[4 * 4608 + j * 72 + i] = mh;   // MT hi  (epilogue B)
        mats[5 * 4608 + j * 72 + i] = ml;   // MT lo
    }
    {
        const float4* atg = reinterpret_cast<const float4*>(
            AT + (size_t)bid * (ROWS_PER_CTA * N_DIM));
        for (int idx = tid; idx < 2048; idx += THREADS) {
            float4 v = atg[idx];
            int r = idx >> 4, c = (idx & 15) << 2;
            float* p = ats + r * AT_STRIDE + c;
            p[0] = v.x; p[1] = v.y; p[2] = v.z; p[3] = v.w;
        }
    }
    // BT cache: col = 8*nt + 2t + h  ->  btv[2*nt + h]
    float btv[16];
    #pragma unroll
    for (int nt = 0; nt < 8; nt++) {
        btv[2 * nt + 0] = fminf(__expf(BTraw[8 * nt + 2 * t + 0]), 1000.0f);
        btv[2 * nt + 1] = fminf(__expf(BTraw[8 * nt + 2 * t + 1]), 1000.0f);
    }
    __syncthreads();

    // ---- fragment registers -------------------------------------------------
    float d[8][4];            // D frags: [nt][c]
    u32 ah[4][4], al[4][4];   // A frags hi/lo: [kt][reg]

    const int rlo = (rb + g) * AT_STRIDE;
    const int rhi = (rb + 8 + g) * AT_STRIDE;

    // initial A = split(AT) from smem
    #pragma unroll
    for (int kt = 0; kt < 4; kt++) {
        int cb = 16 * kt + 2 * t;
        float2 p0 = *reinterpret_cast<const float2*>(ats + rlo + cb);
        float2 p1 = *reinterpret_cast<const float2*>(ats + rhi + cb);
        float2 p2 = *reinterpret_cast<const float2*>(ats + rlo + cb + 8);
        float2 p3 = *reinterpret_cast<const float2*>(ats + rhi + cb + 8);
        split2(p0.x, p0.y, ah[kt][0], al[kt][0]);
        split2(p1.x, p1.y, ah[kt][1], al[kt][1]);
        split2(p2.x, p2.y, ah[kt][2], al[kt][2]);
        split2(p3.x, p3.y, ah[kt][3], al[kt][3]);
    }

    const u32* __restrict__ matw = reinterpret_cast<const u32*>(smc);
    const int gt = 36 * g + t;          // u32 word offset of (n=g, k=2t)

    // Full 3-term split phase; kt-outer so same-accumulator MMAs are >=3 apart
#define MMA_PHASE_FULL(MH)                                                     \
    do {                                                                       \
        _Pragma("unroll")                                                      \
        for (int nt = 0; nt < 8; nt++)                                         \
            _Pragma("unroll")                                                  \
            for (int c = 0; c < 4; c++) d[nt][c] = 0.0f;                       \
        _Pragma("unroll")                                                      \
        for (int kt = 0; kt < 4; kt++) {                                       \
            _Pragma("unroll")                                                  \
            for (int nt = 0; nt < 8; nt++) {                                   \
                const u32* BH = matw + (MH) * 2304 + 288 * nt + gt;            \
                const u32* BL = BH + 2304;                                     \
                u32 bh0 = BH[8 * kt], bh1 = BH[8 * kt + 4];                    \
                u32 bl0 = BL[8 * kt], bl1 = BL[8 * kt + 4];                    \
                MMA(d[nt], ah[kt], bh0, bh1);                                  \
                MMA(d[nt], al[kt], bh0, bh1);                                  \
                MMA(d[nt], ah[kt], bl0, bl1);                                  \
            }                                                                  \
        }                                                                      \
    } while (0)

    // Cheap single-term phase (convergence iterations): Ah * Bh only
#define MMA_PHASE_CHEAP(MH)                                                    \
    do {                                                                       \
        _Pragma("unroll")                                                      \
        for (int nt = 0; nt < 8; nt++)                                         \
            _Pragma("unroll")                                                  \
            for (int c = 0; c < 4; c++) d[nt][c] = 0.0f;                       \
        _Pragma("unroll")                                                      \
        for (int kt = 0; kt < 4; kt++) {                                       \
            _Pragma("unroll")                                                  \
            for (int nt = 0; nt < 8; nt++) {                                   \
                const u32* BH = matw + (MH) * 2304 + 288 * nt + gt;            \
                u32 bh0 = BH[8 * kt], bh1 = BH[8 * kt + 4];                    \
                MMA(d[nt], ah[kt], bh0, bh1);                                  \
            }                                                                  \
        }                                                                      \
    } while (0)

    // repack d (post-nonlinearity fp32) into A frags (in-lane, no shuffle)
#define REPACK()                                                               \
    do {                                                                       \
        _Pragma("unroll")                                                      \
        for (int kt = 0; kt < 4; kt++) {                                       \
            split2(d[2*kt][0],   d[2*kt][1],   ah[kt][0], al[kt][0]);          \
            split2(d[2*kt][2],   d[2*kt][3],   ah[kt][1], al[kt][1]);          \
            split2(d[2*kt+1][0], d[2*kt+1][1], ah[kt][2], al[kt][2]);          \
            split2(d[2*kt+1][2], d[2*kt+1][3], ah[kt][3], al[kt][3]);          \
        }                                                                      \
    } while (0)

    // BF nonlinearity: BF = BT * rcp(S + 1)
#define BF_NONLIN()                                                            \
    do {                                                                       \
        _Pragma("unroll")                                                      \
        for (int nt = 0; nt < 8; nt++) {                                       \
            d[nt][0] = btv[2*nt+0] * rcpa(d[nt][0] + 1.0f);                    \
            d[nt][1] = btv[2*nt+1] * rcpa(d[nt][1] + 1.0f);                    \
            d[nt][2] = btv[2*nt+0] * rcpa(d[nt][2] + 1.0f);                    \
            d[nt][3] = btv[2*nt+1] * rcpa(d[nt][3] + 1.0f);                    \
        }                                                                      \
    } while (0)

    // AF nonlinearity: AF = AT * rcp(T + 1)  (AT re-read from smem)
#define AF_NONLIN()                                                            \
    do {                                                                       \
        _Pragma("unroll")                                                      \
        for (int nt = 0; nt < 8; nt++) {                                       \
            int cb = 8 * nt + 2 * t;                                           \
            float2 plo = *reinterpret_cast<const float2*>(ats + rlo + cb);     \
            float2 phi = *reinterpret_cast<const float2*>(ats + rhi + cb);     \
            d[nt][0] = plo.x * rcpa(d[nt][0] + 1.0f);                          \
            d[nt][1] = plo.y * rcpa(d[nt][1] + 1.0f);                          \
            d[nt][2] = phi.x * rcpa(d[nt][2] + 1.0f);                          \
            d[nt][3] = phi.y * rcpa(d[nt][3] + 1.0f);                          \
        }                                                                      \
    } while (0)

    // ---- phase 1: convergence iterations, single-MMA bf16 ------------------
    #pragma unroll 1
    for (int it = 0; it < PREC_START; ++it) {
        MMA_PHASE_CHEAP(0);   // BF-step (B = KT hi)
        BF_NONLIN();
        REPACK();             // A <- BF
        MMA_PHASE_CHEAP(2);   // AF-step (B = K hi)
        AF_NONLIN();
        REPACK();             // A <- AF
    }

    // ---- phase 2: precision iterations, 3-term split ------------------------
    #pragma unroll 1
    for (int it = PREC_START; it < 22; ++it) {
        MMA_PHASE_FULL(0);    // BF-step
        BF_NONLIN();
        if (it == 21) break;  // d = final BF (fp32); ah/al = final AF
        REPACK();             // A <- BF
        MMA_PHASE_FULL(2);    // AF-step
        AF_NONLIN();
        REPACK();             // A <- AF
    }

    // ---- stash final BF (fp32) into the AT region (AT is dead now) ---------
    #pragma unroll
    for (int nt = 0; nt < 8; nt++) {
        int cb = 8 * nt + 2 * t;
        *reinterpret_cast<float2*>(ats + rlo + cb) =
            make_float2(d[nt][0], d[nt][1]);
        *reinterpret_cast<float2*>(ats + rhi + cb) =
            make_float2(d[nt][2], d[nt][3]);
    }

    // ---- epilogue: H = AF @ M (B = MT mats 4/5); y_r = sum_j BF[r,j] H[r,j]
    MMA_PHASE_FULL(4);

    float y0 = 0.f, y1 = 0.f;
    #pragma unroll
    for (int nt = 0; nt < 8; nt++) {
        int cb = 8 * nt + 2 * t;
        float2 blo = *reinterpret_cast<const float2*>(ats + rlo + cb);
        float2 bhi = *reinterpret_cast<const float2*>(ats + rhi + cb);
        y0 = fmaf(blo.x, d[nt][0], fmaf(blo.y, d[nt][1], y0));
        y1 = fmaf(bhi.x, d[nt][2], fmaf(bhi.y, d[nt][3], y1));
    }

    // reduce over the 4 lanes of each g-group (t = 0..3)
    y0 += __shfl_xor_sync(0xFFFFFFFFu, y0, 1);
    y0 += __shfl_xor_sync(0xFFFFFFFFu, y0, 2);
    y1 += __shfl_xor_sync(0xFFFFFFFFu, y1, 1);
    y1 += __shfl_xor_sync(0xFFFFFFFFu, y1, 2);

    if (t == 0) {
        float bc = fminf(fmaxf(braw[0], -10.0f), 10.0f);
        size_t base = (size_t)bid * ROWS_PER_CTA + rb + g;
        out[base + 0] = y0 + bc;   // row rb + g
        out[base + 8] = y1 + bc;   // row rb + 8 + g
    }
}

extern "C" void kernel_launch(void* const* d_in, const int* in_sizes, int n_in,
                              void* d_out, int out_size)
{
    const float* AT    = (const float*)d_in[0];
    const float* Kraw  = (const float*)d_in[1];
    const float* BTraw = (const float*)d_in[2];
    const float* Wraw  = (const float*)d_in[3];
    const float* braw  = (const float*)d_in[4];
    float* out = (float*)d_out;

    const int B = in_sizes[0] / N_DIM;          // 16384
    const int grid = B / ROWS_PER_CTA;          // 128

    cudaFuncSetAttribute(cnet_mma_kernel,
                         cudaFuncAttributeMaxDynamicSharedMemorySize,
                         SMEM_TOTAL);

    cnet_mma_kernel<<<grid, THREADS, SMEM_TOTAL>>>(
        AT, Kraw, BTraw, Wraw, braw, out);
}

// round 7
// speedup vs baseline: 4.9474x; 1.1394x over previous
#include <cuda_runtime.h>
#include <cuda_bf16.h>
#include <cstdint>
#include <cstddef>

// CompetitiveNetwork via mma.sync (m16n8k16 bf16, fp32 accum).
// R6: (1) fragment-ordered B matrices: one LDS.128 per (nt, kt-pair) replaces
// 4 scalar LDS.32 + addressing; (2) cheap REPACK (ah only) in convergence
// phase, al zeroed at the precision boundary; (3) 14 cheap + 4 precise
// iterations (rel_err margin is ~100x, canary-monitored).
// 8 warps/CTA, 16 rows/warp, state in registers for all steps.

#define THREADS 256
#define ROWS_PER_CTA 128
#define N_DIM 64
#define CHEAP_ITERS 14
#define PREC_ITERS 4

typedef unsigned int u32;

// 6 fragment-ordered matrices of 4096 bf16 (8KB) each:
// 0/1 = KT hi/lo (BF-step), 2/3 = K hi/lo (AF-step), 4/5 = MT hi/lo (epilogue)
#define MATS_BYTES (6 * 8192)              // 49152
#define AT_OFF     MATS_BYTES
#define AT_STRIDE  66                       // f32 words per row
#define SMEM_TOTAL (AT_OFF + 128 * AT_STRIDE * 4)   // 82944

__device__ __forceinline__ float rcpa(float x) {
    float r; asm("rcp.approx.f32 %0, %1;" : "=f"(r) : "f"(x)); return r;
}
__device__ __forceinline__ u32 packbf(float lo_elem, float hi_elem) {
    u32 r; asm("cvt.rn.bf16x2.f32 %0, %1, %2;" : "=r"(r)
               : "f"(hi_elem), "f"(lo_elem));
    return r;
}
__device__ __forceinline__ void split2(float x0, float x1, u32 &hi, u32 &lo) {
    hi = packbf(x0, x1);
    float h0 = __uint_as_float(hi << 16);
    float h1 = __uint_as_float(hi & 0xFFFF0000u);
    lo = packbf(x0 - h0, x1 - h1);
}

// fragment-order store: element at logical (k, n) of the B operand
// idx = sel*2048 + nt*256 + lane*8 + w2*2 + (k&1), lane = 4*(n&7) + ((k&7)>>1)
__device__ __forceinline__ void st_frag(__nv_bfloat16* base, int k, int n,
                                        __nv_bfloat16 v) {
    int lane = ((n & 7) << 2) | ((k & 7) >> 1);
    int w2   = (((k >> 4) & 1) << 1) | ((k >> 3) & 1);
    int idx  = ((k >> 5) << 11) | ((n >> 3) << 8) | (lane << 3)
             | (w2 << 1) | (k & 1);
    base[idx] = v;
}

#define MMA(d, a, b0, b1)                                                      \
    asm("mma.sync.aligned.m16n8k16.row.col.f32.bf16.bf16.f32 "                 \
        "{%0,%1,%2,%3}, {%4,%5,%6,%7}, {%8,%9}, {%0,%1,%2,%3};"                \
        : "+f"((d)[0]), "+f"((d)[1]), "+f"((d)[2]), "+f"((d)[3])               \
        : "r"((a)[0]), "r"((a)[1]), "r"((a)[2]), "r"((a)[3]),                  \
          "r"(b0), "r"(b1))

__global__ void __launch_bounds__(THREADS, 1)
cnet_mma_kernel(const float* __restrict__ AT,
                const float* __restrict__ Kraw,
                const float* __restrict__ BTraw,
                const float* __restrict__ Wraw,
                const float* __restrict__ braw,
                float* __restrict__ out)
{
    extern __shared__ char smc[];
    __nv_bfloat16* mats = reinterpret_cast<__nv_bfloat16*>(smc);
    float* ats = reinterpret_cast<float*>(smc + AT_OFF);   // [128][66] f32

    const int tid  = threadIdx.x;
    const int w    = tid >> 5;          // warp 0..7 -> rows [16w, 16w+16)
    const int lane = tid & 31;
    const int g    = lane >> 2;         // group row 0..7
    const int t    = lane & 3;          // thread-in-group 0..3
    const int rb   = w * 16;            // warp row base (CTA-local)
    const int bid  = blockIdx.x;

    // ---- setup: exp/clip K, fragment-ordered split B matrices + AT tile ----
    for (int idx = tid; idx < 4096; idx += THREADS) {
        int i = idx >> 6, j = idx & 63;
        float k = fminf(__expf(Kraw[idx]), 1000.0f);
        float wv = fminf(fmaxf(Wraw[idx], -10.0f), 10.0f);
        float m = k * wv;
        __nv_bfloat16 kh = __float2bfloat16_rn(k);
        __nv_bfloat16 kl = __float2bfloat16_rn(k - __bfloat162float(kh));
        __nv_bfloat16 mh = __float2bfloat16_rn(m);
        __nv_bfloat16 ml = __float2bfloat16_rn(m - __bfloat162float(mh));
        st_frag(mats + 0 * 4096, i, j, kh);   // KT hi: B[k=i][n=j] (BF-step)
        st_frag(mats + 1 * 4096, i, j, kl);   // KT lo
        st_frag(mats + 2 * 4096, j, i, kh);   // K  hi: B[k=j][n=i] (AF-step)
        st_frag(mats + 3 * 4096, j, i, kl);   // K  lo
        st_frag(mats + 4 * 4096, i, j, mh);   // MT hi: B[k=i][n=j] (epilogue)
        st_frag(mats + 5 * 4096, i, j, ml);   // MT lo
    }
    {
        const float4* atg = reinterpret_cast<const float4*>(
            AT + (size_t)bid * (ROWS_PER_CTA * N_DIM));
        for (int idx = tid; idx < 2048; idx += THREADS) {
            float4 v = atg[idx];
            int r = idx >> 4, c = (idx & 15) << 2;
            float* p = ats + r * AT_STRIDE + c;
            p[0] = v.x; p[1] = v.y; p[2] = v.z; p[3] = v.w;
        }
    }
    // BT cache: col = 8*nt + 2t + h  ->  btv[2*nt + h]
    float btv[16];
    #pragma unroll
    for (int nt = 0; nt < 8; nt++) {
        btv[2 * nt + 0] = fminf(__expf(BTraw[8 * nt + 2 * t + 0]), 1000.0f);
        btv[2 * nt + 1] = fminf(__expf(BTraw[8 * nt + 2 * t + 1]), 1000.0f);
    }
    __syncthreads();

    // ---- fragment registers -------------------------------------------------
    float d[8][4];            // D frags: [nt][c]
    u32 ah[4][4], al[4][4];   // A frags hi/lo: [kt][reg]

    const int rlo = (rb + g) * AT_STRIDE;
    const int rhi = (rb + 8 + g) * AT_STRIDE;

    // initial A = split(AT) from smem
    #pragma unroll
    for (int kt = 0; kt < 4; kt++) {
        int cb = 16 * kt + 2 * t;
        float2 p0 = *reinterpret_cast<const float2*>(ats + rlo + cb);
        float2 p1 = *reinterpret_cast<const float2*>(ats + rhi + cb);
        float2 p2 = *reinterpret_cast<const float2*>(ats + rlo + cb + 8);
        float2 p3 = *reinterpret_cast<const float2*>(ats + rhi + cb + 8);
        split2(p0.x, p0.y, ah[kt][0], al[kt][0]);
        split2(p1.x, p1.y, ah[kt][1], al[kt][1]);
        split2(p2.x, p2.y, ah[kt][2], al[kt][2]);
        split2(p3.x, p3.y, ah[kt][3], al[kt][3]);
    }

    // per-thread fragment pointer: uint4 index = m*512 + sel*256 + nt*32 + lane
    const uint4* __restrict__ frag = reinterpret_cast<const uint4*>(smc) + lane;

    // Full 3-term split phase (hi matrix MH, lo matrix MH+1)
#define MMA_PHASE_FULL(MH)                                                     \
    do {                                                                       \
        _Pragma("unroll")                                                      \
        for (int nt = 0; nt < 8; nt++)                                         \
            _Pragma("unroll")                                                  \
            for (int c = 0; c < 4; c++) d[nt][c] = 0.0f;                       \
        _Pragma("unroll")                                                      \
        for (int sel = 0; sel < 2; sel++) {                                    \
            _Pragma("unroll")                                                  \
            for (int nt = 0; nt < 8; nt++) {                                   \
                uint4 h = frag[(MH) * 512 + sel * 256 + nt * 32];              \
                uint4 l = frag[((MH) + 1) * 512 + sel * 256 + nt * 32];        \
                MMA(d[nt], ah[2*sel],   h.x, h.y);                             \
                MMA(d[nt], al[2*sel],   h.x, h.y);                             \
                MMA(d[nt], ah[2*sel],   l.x, l.y);                             \
                MMA(d[nt], ah[2*sel+1], h.z, h.w);                             \
                MMA(d[nt], al[2*sel+1], h.z, h.w);                             \
                MMA(d[nt], ah[2*sel+1], l.z, l.w);                             \
            }                                                                  \
        }                                                                      \
    } while (0)

    // Cheap single-term phase (convergence iterations): Ah * Bh only
#define MMA_PHASE_CHEAP(MH)                                                    \
    do {                                                                       \
        _Pragma("unroll")                                                      \
        for (int nt = 0; nt < 8; nt++)                                         \
            _Pragma("unroll")                                                  \
            for (int c = 0; c < 4; c++) d[nt][c] = 0.0f;                       \
        _Pragma("unroll")                                                      \
        for (int sel = 0; sel < 2; sel++) {                                    \
            _Pragma("unroll")                                                  \
            for (int nt = 0; nt < 8; nt++) {                                   \
                uint4 h = frag[(MH) * 512 + sel * 256 + nt * 32];              \
                MMA(d[nt], ah[2*sel],   h.x, h.y);                             \
                MMA(d[nt], ah[2*sel+1], h.z, h.w);                             \
            }                                                                  \
        }                                                                      \
    } while (0)

    // full repack: d -> (ah, al)
#define REPACK()                                                               \
    do {                                                                       \
        _Pragma("unroll")                                                      \
        for (int kt = 0; kt < 4; kt++) {                                       \
            split2(d[2*kt][0],   d[2*kt][1],   ah[kt][0], al[kt][0]);          \
            split2(d[2*kt][2],   d[2*kt][3],   ah[kt][1], al[kt][1]);          \
            split2(d[2*kt+1][0], d[2*kt+1][1], ah[kt][2], al[kt][2]);          \
            split2(d[2*kt+1][2], d[2*kt+1][3], ah[kt][3], al[kt][3]);          \
        }                                                                      \
    } while (0)

    // cheap repack: d -> ah only (al not consumed in cheap phase)
#define REPACK_CHEAP()                                                         \
    do {                                                                       \
        _Pragma("unroll")                                                      \
        for (int kt = 0; kt < 4; kt++) {                                       \
            ah[kt][0] = packbf(d[2*kt][0],   d[2*kt][1]);                      \
            ah[kt][1] = packbf(d[2*kt][2],   d[2*kt][3]);                      \
            ah[kt][2] = packbf(d[2*kt+1][0], d[2*kt+1][1]);                    \
            ah[kt][3] = packbf(d[2*kt+1][2], d[2*kt+1][3]);                    \
        }                                                                      \
    } while (0)

#define BF_NONLIN()                                                            \
    do {                                                                       \
        _Pragma("unroll")                                                      \
        for (int nt = 0; nt < 8; nt++) {                                       \
            d[nt][0] = btv[2*nt+0] * rcpa(d[nt][0] + 1.0f);                    \
            d[nt][1] = btv[2*nt+1] * rcpa(d[nt][1] + 1.0f);                    \
            d[nt][2] = btv[2*nt+0] * rcpa(d[nt][2] + 1.0f);                    \
            d[nt][3] = btv[2*nt+1] * rcpa(d[nt][3] + 1.0f);                    \
        }                                                                      \
    } while (0)

#define AF_NONLIN()                                                            \
    do {                                                                       \
        _Pragma("unroll")                                                      \
        for (int nt = 0; nt < 8; nt++) {                                       \
            int cb = 8 * nt + 2 * t;                                           \
            float2 plo = *reinterpret_cast<const float2*>(ats + rlo + cb);     \
            float2 phi = *reinterpret_cast<const float2*>(ats + rhi + cb);     \
            d[nt][0] = plo.x * rcpa(d[nt][0] + 1.0f);                          \
            d[nt][1] = plo.y * rcpa(d[nt][1] + 1.0f);                          \
            d[nt][2] = phi.x * rcpa(d[nt][2] + 1.0f);                          \
            d[nt][3] = phi.y * rcpa(d[nt][3] + 1.0f);                          \
        }                                                                      \
    } while (0)

    // ---- phase 1: convergence iterations, single-MMA bf16 ------------------
    #pragma unroll 1
    for (int it = 0; it < CHEAP_ITERS; ++it) {
        MMA_PHASE_CHEAP(0);   // BF-step (B = KT hi)
        BF_NONLIN();
        REPACK_CHEAP();       // A <- BF (hi only)
        MMA_PHASE_CHEAP(2);   // AF-step (B = K hi)
        AF_NONLIN();
        REPACK_CHEAP();       // A <- AF (hi only)
    }

    // precision boundary: al holds stale values from the initial AT split
    #pragma unroll
    for (int kt = 0; kt < 4; kt++)
        #pragma unroll
        for (int r = 0; r < 4; r++) al[kt][r] = 0u;

    // ---- phase 2: precision iterations, 3-term split ------------------------
    #pragma unroll 1
    for (int it = 0; it < PREC_ITERS; ++it) {
        MMA_PHASE_FULL(0);    // BF-step
        BF_NONLIN();
        if (it == PREC_ITERS - 1) break;  // d = final BF; ah/al = final AF
        REPACK();             // A <- BF
        MMA_PHASE_FULL(2);    // AF-step
        AF_NONLIN();
        REPACK();             // A <- AF
    }

    // ---- stash final BF (fp32) into the AT region (AT is dead now) ---------
    #pragma unroll
    for (int nt = 0; nt < 8; nt++) {
        int cb = 8 * nt + 2 * t;
        *reinterpret_cast<float2*>(ats + rlo + cb) =
            make_float2(d[nt][0], d[nt][1]);
        *reinterpret_cast<float2*>(ats + rhi + cb) =
            make_float2(d[nt][2], d[nt][3]);
    }

    // ---- epilogue: H = AF @ M (B = MT mats 4/5); y_r = sum_j BF[r,j] H[r,j]
    MMA_PHASE_FULL(4);

    float y0 = 0.f, y1 = 0.f;
    #pragma unroll
    for (int nt = 0; nt < 8; nt++) {
        int cb = 8 * nt + 2 * t;
        float2 blo = *reinterpret_cast<const float2*>(ats + rlo + cb);
        float2 bhi = *reinterpret_cast<const float2*>(ats + rhi + cb);
        y0 = fmaf(blo.x, d[nt][0], fmaf(blo.y, d[nt][1], y0));
        y1 = fmaf(bhi.x, d[nt][2], fmaf(bhi.y, d[nt][3], y1));
    }

    // reduce over the 4 lanes of each g-group (t = 0..3)
    y0 += __shfl_xor_sync(0xFFFFFFFFu, y0, 1);
    y0 += __shfl_xor_sync(0xFFFFFFFFu, y0, 2);
    y1 += __shfl_xor_sync(0xFFFFFFFFu, y1, 1);
    y1 += __shfl_xor_sync(0xFFFFFFFFu, y1, 2);

    if (t == 0) {
        float bc = fminf(fmaxf(braw[0], -10.0f), 10.0f);
        size_t base = (size_t)bid * ROWS_PER_CTA + rb + g;
        out[base + 0] = y0 + bc;   // row rb + g
        out[base + 8] = y1 + bc;   // row rb + 8 + g
    }
}

extern "C" void kernel_launch(void* const* d_in, const int* in_sizes, int n_in,
                              void* d_out, int out_size)
{
    const float* AT    = (const float*)d_in[0];
    const float* Kraw  = (const float*)d_in[1];
    const float* BTraw = (const float*)d_in[2];
    const float* Wraw  = (const float*)d_in[3];
    const float* braw  = (const float*)d_in[4];
    float* out = (float*)d_out;

    const int B = in_sizes[0] / N_DIM;          // 16384
    const int grid = B / ROWS_PER_CTA;          // 128

    cudaFuncSetAttribute(cnet_mma_kernel,
                         cudaFuncAttributeMaxDynamicSharedMemorySize,
                         SMEM_TOTAL);

    cnet_mma_kernel<<<grid, THREADS, SMEM_TOTAL>>>(
        AT, Kraw, BTraw, Wraw, braw, out);
}